// round 12
// baseline (speedup 1.0000x reference)
#include <cuda_runtime.h>
#include <math.h>
#include <stdint.h>

// VanillaRNN persistent kernel, v7: mma.sync TF32 3-product split +
// ASYNC column-group handoff (no per-step grid barrier).
// 128 CTAs, CTA tile 64(batch) x 32(cols), K=512, 4 chunks of 128 k.
// 16 warps: k-split 8 x m-split 2 (v6-validated fragment mapping).
// h read via __ldcg (L2-direct) -> no stale-L1; producers publish via
// fence + atomicAdd on monotonic per-colgroup counters.

#define CBX 16     // column blocks (512/32)
#define RBY 8      // row blocks    (512/64)
#define NCTA (CBX*RBY)
#define NTHR 512

constexpr int S = 1024, H = 512, OUTD = 10;
constexpr int BM = 64, BN = 32;
constexpr int NCH = 4;                        // 512/128 k-chunks

// smem byte offsets
constexpr int SM_XS = 0;                      // 64 floats x[:,t]
constexpr int SM_WX = 256;                    // 32 floats W_hx
constexpr int SM_BB = 384;                    // 32 floats b_hx+b_hh
constexpr int SM_A  = 1024;                   // A fp32: [2 buf][64 rows][132]
constexpr int A_BUF = 64 * 132 * 4;           // 33792 B
constexpr int SM_B  = SM_A + 2 * A_BUF;       // 68608
constexpr int B_PLANE = 64 * 2 * 32 * 16;     // 65536 B
constexpr int SMEM_BYTES = SM_B + 2 * B_PLANE;   // 199680 B

__device__ __align__(16) float g_h[2][H * H]; // ping-pong hidden state (row-major)
__device__ unsigned g_arrive = 0;
__device__ unsigned g_phase  = 0;
__device__ unsigned g_cnt[CBX];               // monotonic colgroup counters (reset at end)

__device__ __forceinline__ void grid_barrier(unsigned v) {
    __syncthreads();
    if (threadIdx.x == 0) {
        __threadfence();
        unsigned prev = atomicAdd(&g_arrive, 1u);
        if (prev == (unsigned)(NCTA - 1)) {
            *(volatile unsigned*)&g_arrive = 0u;
            __threadfence();
            *(volatile unsigned*)&g_phase = v;
        } else {
            while (*(volatile unsigned*)&g_phase != v) { }
        }
        __threadfence();
    }
    __syncthreads();
}

__device__ __forceinline__ unsigned ld_acq(const unsigned* p) {
    unsigned v;
    asm volatile("ld.acquire.gpu.u32 %0, [%1];" : "=r"(v) : "l"(p) : "memory");
    return v;
}
__device__ __forceinline__ float tf32_rna(float v) {
    float r; asm("cvt.rna.tf32.f32 %0, %1;" : "=f"(r) : "f"(v)); return r;
}
__device__ __forceinline__ uint32_t fu(float v) { return __float_as_uint(v); }

__device__ __forceinline__ void mma8(float d[4], uint32_t a0, uint32_t a1,
                                     uint32_t a2, uint32_t a3,
                                     uint32_t b0, uint32_t b1) {
    asm volatile(
        "mma.sync.aligned.m16n8k8.row.col.f32.tf32.tf32.f32 "
        "{%0,%1,%2,%3},{%4,%5,%6,%7},{%8,%9},{%0,%1,%2,%3};"
        : "+f"(d[0]), "+f"(d[1]), "+f"(d[2]), "+f"(d[3])
        : "r"(a0), "r"(a1), "r"(a2), "r"(a3), "r"(b0), "r"(b1));
}
__device__ __forceinline__ float ftanh(float v) {
    float e = __expf(2.0f * v);
    return 1.0f - __fdividef(2.0f, e + 1.0f);
}

__global__ void __launch_bounds__(NTHR, 1)
rnn_kernel(const float* __restrict__ x,    const float* __restrict__ W_hx,
           const float* __restrict__ b_hx, const float* __restrict__ W_hh,
           const float* __restrict__ b_hh, const float* __restrict__ W_oh,
           const float* __restrict__ b_oh, float* __restrict__ out)
{
    extern __shared__ char smem[];
    float* xs  = (float*)(smem + SM_XS);
    float* wxs = (float*)(smem + SM_WX);
    float* bbs = (float*)(smem + SM_BB);

    const int tid = threadIdx.x, lane = tid & 31, wid = tid >> 5;
    const int cb = blockIdx.x, rb = blockIdx.y;
    const int row0 = rb * BM, col0 = cb * BN;
    const int kg = wid & 7;                 // k-group: k8 blocks c*16 + kg*2 + {0,1}
    const int mg = wid >> 3;                // m-half: rows [mg*32, mg*32+32)

    // Build fragment-ready B (hi/lo tf32) once; resident for all 1024 steps.
    for (int i = tid; i < 4096; i += NTHR) {
        int ln = i & 31, np = (i >> 5) & 1, kb = i >> 6;
        int k0 = kb * 8 + (ln & 3);
        const float* wr0 = W_hh + (col0 + np * 16 + (ln >> 2)) * H;
        const float* wr1 = wr0 + 8 * H;
        float w00 = wr0[k0], w01 = wr0[k0 + 4];
        float w10 = wr1[k0], w11 = wr1[k0 + 4];
        float4 hi, lo;
        hi.x = tf32_rna(w00); lo.x = tf32_rna(w00 - hi.x);
        hi.y = tf32_rna(w01); lo.y = tf32_rna(w01 - hi.y);
        hi.z = tf32_rna(w10); lo.z = tf32_rna(w10 - hi.z);
        hi.w = tf32_rna(w11); lo.w = tf32_rna(w11 - hi.w);
        *(float4*)(smem + SM_B + i * 16)           = hi;
        *(float4*)(smem + SM_B + B_PLANE + i * 16) = lo;
    }
    if (tid < BN) {
        wxs[tid] = W_hx[col0 + tid];
        bbs[tid] = b_hx[col0 + tid] + b_hh[col0 + tid];
    }
    {   // h0 = zeros; each CTA zeroes a disjoint 1/128 slice
        int cta = rb * CBX + cb;
        for (int i = tid; i < 2048; i += NTHR) g_h[0][cta * 2048 + i] = 0.0f;
    }
    grid_barrier(1u);

    // staging roles: rows srow, srow+32; k-float4 sfc and sfc+16 within a 128-k chunk
    const int srow = tid >> 4, sfc = tid & 15;
    const int gb   = sfc >> 3;              // colgroup offset for this thread's slices
    // fragment base (bytes): row mg*32 + lane/4, k word lane%3... (k-major stride 132)
    const int aoff = ((mg * 32 + (lane >> 2)) * 132 + (lane & 3)) * 4;

    for (int t = 0; t < S; ++t) {
        const float* hin  = g_h[t & 1];
        float*       hout = g_h[(t + 1) & 1];
        if (tid < BM) xs[tid] = x[(row0 + tid) * S + t];
        const unsigned tgt = 8u * (unsigned)t;

        const float* hp0 = hin + (row0 + srow) * H + sfc * 4;
        const float* hp1 = hp0 + 32 * H;

        {   // poll cols for chunk 0, stage into buf 0 (L2-direct loads)
            while (ld_acq(&g_cnt[gb])     < tgt) {}
            while (ld_acq(&g_cnt[gb + 2]) < tgt) {}
            float4 a0 = __ldcg((const float4*)(hp0));
            float4 a1 = __ldcg((const float4*)(hp0 + 64));
            float4 b0 = __ldcg((const float4*)(hp1));
            float4 b1 = __ldcg((const float4*)(hp1 + 64));
            char* base = smem + SM_A;
            *(float4*)(base + (srow * 132 + sfc * 4) * 4)          = a0;
            *(float4*)(base + (srow * 132 + (sfc + 16) * 4) * 4)   = a1;
            *(float4*)(base + ((srow + 32) * 132 + sfc * 4) * 4)        = b0;
            *(float4*)(base + ((srow + 32) * 132 + (sfc + 16) * 4) * 4) = b1;
        }

        float D[2][4][4];
        #pragma unroll
        for (int rg = 0; rg < 2; ++rg)
            #pragma unroll
            for (int nb = 0; nb < 4; ++nb)
                #pragma unroll
                for (int r = 0; r < 4; ++r) D[rg][nb][r] = 0.0f;

        float4 pa0, pa1, pb0, pb1;
        #pragma unroll
        for (int c = 0; c < NCH; ++c) {
            __syncthreads();                   // chunk c staged; buf (c+1)&1 free
            if (c + 1 < NCH) {                 // poll + prefetch next chunk (L2)
                int g1 = 4 * (c + 1) + gb;
                while (ld_acq(&g_cnt[g1])     < tgt) {}
                while (ld_acq(&g_cnt[g1 + 2]) < tgt) {}
                pa0 = __ldcg((const float4*)(hp0 + (c + 1) * 128));
                pa1 = __ldcg((const float4*)(hp0 + (c + 1) * 128 + 64));
                pb0 = __ldcg((const float4*)(hp1 + (c + 1) * 128));
                pb1 = __ldcg((const float4*)(hp1 + (c + 1) * 128 + 64));
            }
            const char* abc = smem + SM_A + (c & 1) * A_BUF + aoff;
            #pragma unroll
            for (int j = 0; j < 2; ++j) {
                const char* bbp = smem + SM_B
                                + (size_t)(c * 16 + kg * 2 + j) * 1024 + lane * 16;
                float4 bh0 = *(const float4*)(bbp);
                float4 bh1 = *(const float4*)(bbp + 512);
                float4 bl0 = *(const float4*)(bbp + B_PLANE);
                float4 bl1 = *(const float4*)(bbp + B_PLANE + 512);
                uint32_t BH[8] = { fu(bh0.x), fu(bh0.y), fu(bh0.z), fu(bh0.w),
                                   fu(bh1.x), fu(bh1.y), fu(bh1.z), fu(bh1.w) };
                uint32_t BL[8] = { fu(bl0.x), fu(bl0.y), fu(bl0.z), fu(bl0.w),
                                   fu(bl1.x), fu(bl1.y), fu(bl1.z), fu(bl1.w) };
                const char* ab = abc + (kg * 16 + j * 8) * 4;
                #pragma unroll
                for (int rg = 0; rg < 2; ++rg) {
                    const char* ar = ab + rg * (16 * 132 * 4);
                    float f0 = *(const float*)(ar);
                    float f1 = *(const float*)(ar + 8 * 132 * 4);
                    float f2 = *(const float*)(ar + 16);
                    float f3 = *(const float*)(ar + 8 * 132 * 4 + 16);
                    float h0 = tf32_rna(f0), h1 = tf32_rna(f1);
                    float h2 = tf32_rna(f2), h3 = tf32_rna(f3);
                    uint32_t ah0 = fu(h0), ah1 = fu(h1), ah2 = fu(h2), ah3 = fu(h3);
                    uint32_t al0 = fu(f0 - h0), al1 = fu(f1 - h1);
                    uint32_t al2 = fu(f2 - h2), al3 = fu(f3 - h3);
                    #pragma unroll
                    for (int nb = 0; nb < 4; ++nb) {
                        mma8(D[rg][nb], ah0, ah1, ah2, ah3, BH[2*nb], BH[2*nb+1]);
                        mma8(D[rg][nb], al0, al1, al2, al3, BH[2*nb], BH[2*nb+1]);
                        mma8(D[rg][nb], ah0, ah1, ah2, ah3, BL[2*nb], BL[2*nb+1]);
                    }
                }
            }
            if (c + 1 < NCH) {
                char* base = smem + SM_A + ((c + 1) & 1) * A_BUF;
                *(float4*)(base + (srow * 132 + sfc * 4) * 4)          = pa0;
                *(float4*)(base + (srow * 132 + (sfc + 16) * 4) * 4)   = pa1;
                *(float4*)(base + ((srow + 32) * 132 + sfc * 4) * 4)        = pb0;
                *(float4*)(base + ((srow + 32) * 132 + (sfc + 16) * 4) * 4) = pb1;
            }
        }
        __syncthreads();                       // compute done; A buffers reusable

        // scatter k-partials: mg0 -> buf0 region, mg1 -> buf1 region
        {
            float4* scr = (float4*)(smem + SM_A + mg * A_BUF);
            #pragma unroll
            for (int rg = 0; rg < 2; ++rg)
                #pragma unroll
                for (int nb = 0; nb < 4; ++nb)
                    scr[kg * 256 + rg * 128 + nb * 32 + lane] =
                        make_float4(D[rg][nb][0], D[rg][nb][1],
                                    D[rg][nb][2], D[rg][nb][3]);
        }
        __syncthreads();

        // Reduce 8 k-partials + epilogue: each thread finishes 4 outputs.
        {
            int mgp = tid >> 8, idx = tid & 255;
            const float4* scr = (const float4*)(smem + SM_A + mgp * A_BUF);
            float4 v = scr[idx];
            #pragma unroll
            for (int k2 = 1; k2 < 8; ++k2) {
                float4 p = scr[k2 * 256 + idx];
                v.x += p.x; v.y += p.y; v.z += p.z; v.w += p.w;
            }
            int rg = idx >> 7, nb = (idx >> 5) & 3, ln = idx & 31;
            int r1 = mgp * 32 + rg * 16 + (ln >> 2);
            int jc = nb * 8 + 2 * (ln & 3);
            float xv1 = xs[r1], xv2 = xs[r1 + 8];
            float wj0 = wxs[jc], wj1 = wxs[jc + 1];
            float bj0 = bbs[jc], bj1 = bbs[jc + 1];
            float2 o1, o2;
            o1.x = ftanh(fmaf(xv1, wj0, v.x) + bj0);
            o1.y = ftanh(fmaf(xv1, wj1, v.y) + bj1);
            o2.x = ftanh(fmaf(xv2, wj0, v.z) + bj0);
            o2.y = ftanh(fmaf(xv2, wj1, v.w) + bj1);
            *(float2*)(hout + (row0 + r1) * H + col0 + jc)     = o1;
            *(float2*)(hout + (row0 + r1 + 8) * H + col0 + jc) = o2;
        }
        __syncthreads();                       // all epilogue stores issued
        if (tid == 0) {                        // publish: cols [col0,col0+32) @ level t+1
            __threadfence();
            atomicAdd(&g_cnt[cb], 1u);
        }
    }

    grid_barrier(2u);
    if (cb == 0 && rb == 0 && tid < CBX) g_cnt[tid] = 0u;   // replay-safe reset

    // Final projection + softmax: cb==0 CTAs handle their 64 rows. h final in g_h[0].
    if (cb == 0) {
        float* wo = (float*)(smem + SM_A);              // 5120 floats
        for (int i = tid; i < OUTD * H; i += NTHR) wo[i] = W_oh[i];
        __syncthreads();
        const float* hf = g_h[0];
        int r = tid >> 3, q = tid & 7;                  // 8 threads/row, 64 k each
        float p[OUTD];
        #pragma unroll
        for (int od = 0; od < OUTD; ++od) p[od] = 0.f;
        const float* hr = hf + (row0 + r) * H + q * 64;
        for (int k = 0; k < 64; k += 4) {
            float4 hv = *(const float4*)(hr + k);
            #pragma unroll
            for (int od = 0; od < OUTD; ++od) {
                const float* wr = wo + od * H + q * 64 + k;
                p[od] += hv.x * wr[0] + hv.y * wr[1] + hv.z * wr[2] + hv.w * wr[3];
            }
        }
        float* pr = (float*)(smem + SM_A + 20480);      // 512 x 10 partials
        #pragma unroll
        for (int od = 0; od < OUTD; ++od) pr[tid * OUTD + od] = p[od];
        __syncthreads();
        if (tid < BM) {
            float o[OUTD];
            #pragma unroll
            for (int od = 0; od < OUTD; ++od) {
                float s0 = 0.f;
                #pragma unroll
                for (int j = 0; j < 8; ++j)
                    s0 += pr[(8 * tid + j) * OUTD + od];
                o[od] = s0 + b_oh[od];
            }
            float mx = o[0];
            #pragma unroll
            for (int od = 1; od < OUTD; ++od) mx = fmaxf(mx, o[od]);
            float ssum = 0.f;
            #pragma unroll
            for (int od = 0; od < OUTD; ++od) { o[od] = expf(o[od] - mx); ssum += o[od]; }
            float inv = 1.0f / ssum;
            #pragma unroll
            for (int od = 0; od < OUTD; ++od)
                out[(row0 + tid) * OUTD + od] = o[od] * inv;
        }
    }
}

extern "C" void kernel_launch(void* const* d_in, const int* in_sizes, int n_in,
                              void* d_out, int out_size) {
    const float* x    = (const float*)d_in[0];
    const float* W_hx = (const float*)d_in[1];
    const float* b_hx = (const float*)d_in[2];
    const float* W_hh = (const float*)d_in[3];
    const float* b_hh = (const float*)d_in[4];
    const float* W_oh = (const float*)d_in[5];
    const float* b_oh = (const float*)d_in[6];
    float* out = (float*)d_out;

    cudaFuncSetAttribute(rnn_kernel, cudaFuncAttributeMaxDynamicSharedMemorySize, SMEM_BYTES);
    rnn_kernel<<<dim3(CBX, RBY, 1), NTHR, SMEM_BYTES>>>(x, W_hx, b_hx, W_hh, b_hh, W_oh, b_oh, out);
}

// round 13
// speedup vs baseline: 1.5096x; 1.5096x over previous
#include <cuda_runtime.h>
#include <math.h>
#include <stdint.h>

// VanillaRNN persistent kernel, v8: mma.sync TF32 3-product split +
// per-row-strip barriers (batch rows are independent across strips).
// 128 CTAs = 8 strips x 16 col-blocks. CTA tile 64(batch) x 32(cols), K=512.
// 16 warps: k-split 8 x m-split 2. 4 chunks of 128 k, double-buffered smem,
// register prefetch. B (W_hh hi/lo tf32) fragment-resident all 1024 steps.

#define CBX 16     // column blocks (512/32)
#define RBY 8      // row strips    (512/64)
#define NCTA (CBX*RBY)
#define NTHR 512

constexpr int S = 1024, H = 512, OUTD = 10;
constexpr int BM = 64, BN = 32;
constexpr int NCH = 4;                        // 512/128 k-chunks

// smem byte offsets
constexpr int SM_XS = 0;                      // 64 floats x[:,t]
constexpr int SM_WX = 256;                    // 32 floats W_hx
constexpr int SM_BB = 384;                    // 32 floats b_hx+b_hh
constexpr int SM_A  = 1024;                   // A fp32: [2 buf][64 rows][132]
constexpr int A_BUF = 64 * 132 * 4;           // 33792 B
constexpr int SM_B  = SM_A + 2 * A_BUF;       // 68608
constexpr int B_PLANE = 64 * 2 * 32 * 16;     // 65536 B
constexpr int SMEM_BYTES = SM_B + 2 * B_PLANE;   // 199680 B

__device__ __align__(16) float g_h[2][H * H]; // ping-pong hidden state (row-major)
__device__ unsigned g_arrive = 0;             // global barrier (init/final only)
__device__ unsigned g_phase  = 0;
__device__ unsigned g_sarr[RBY][32];          // per-strip arrive ctr (128B padded)
__device__ unsigned g_sph[RBY][32];           // per-strip phase     (128B padded)

__device__ __forceinline__ void grid_barrier(unsigned v) {
    __syncthreads();
    if (threadIdx.x == 0) {
        __threadfence();
        unsigned prev = atomicAdd(&g_arrive, 1u);
        if (prev == (unsigned)(NCTA - 1)) {
            *(volatile unsigned*)&g_arrive = 0u;
            __threadfence();
            *(volatile unsigned*)&g_phase = v;
        } else {
            while (*(volatile unsigned*)&g_phase != v) { }
        }
        __threadfence();
    }
    __syncthreads();
}

// Phase-exact 16-CTA strip barrier; last call of the run publishes 0 (replay-safe).
__device__ __forceinline__ void strip_barrier(int rb, unsigned v) {
    __syncthreads();
    if (threadIdx.x == 0) {
        __threadfence();
        unsigned prev = atomicAdd(&g_sarr[rb][0], 1u);
        if (prev == (unsigned)(CBX - 1)) {
            *(volatile unsigned*)&g_sarr[rb][0] = 0u;
            __threadfence();
            *(volatile unsigned*)&g_sph[rb][0] = v;
        } else {
            while (*(volatile unsigned*)&g_sph[rb][0] != v) { }
        }
        __threadfence();
    }
    __syncthreads();
}

__device__ __forceinline__ float tf32_rna(float v) {
    float r; asm("cvt.rna.tf32.f32 %0, %1;" : "=f"(r) : "f"(v)); return r;
}
__device__ __forceinline__ uint32_t fu(float v) { return __float_as_uint(v); }

__device__ __forceinline__ void mma8(float d[4], uint32_t a0, uint32_t a1,
                                     uint32_t a2, uint32_t a3,
                                     uint32_t b0, uint32_t b1) {
    asm volatile(
        "mma.sync.aligned.m16n8k8.row.col.f32.tf32.tf32.f32 "
        "{%0,%1,%2,%3},{%4,%5,%6,%7},{%8,%9},{%0,%1,%2,%3};"
        : "+f"(d[0]), "+f"(d[1]), "+f"(d[2]), "+f"(d[3])
        : "r"(a0), "r"(a1), "r"(a2), "r"(a3), "r"(b0), "r"(b1));
}
__device__ __forceinline__ float ftanh(float v) {
    float e = __expf(2.0f * v);
    return 1.0f - __fdividef(2.0f, e + 1.0f);
}

__global__ void __launch_bounds__(NTHR, 1)
rnn_kernel(const float* __restrict__ x,    const float* __restrict__ W_hx,
           const float* __restrict__ b_hx, const float* __restrict__ W_hh,
           const float* __restrict__ b_hh, const float* __restrict__ W_oh,
           const float* __restrict__ b_oh, float* __restrict__ out)
{
    extern __shared__ char smem[];
    float* xs  = (float*)(smem + SM_XS);
    float* wxs = (float*)(smem + SM_WX);
    float* bbs = (float*)(smem + SM_BB);

    const int tid = threadIdx.x, lane = tid & 31, wid = tid >> 5;
    const int cb = blockIdx.x, rb = blockIdx.y;
    const int row0 = rb * BM, col0 = cb * BN;
    const int kg = wid & 7;                 // k-group: k8 blocks c*16 + kg*2 + {0,1}
    const int mg = wid >> 3;                // m-half: rows [mg*32, mg*32+32)

    // Build fragment-ready B (hi/lo tf32) once; resident for all 1024 steps.
    for (int i = tid; i < 4096; i += NTHR) {
        int ln = i & 31, np = (i >> 5) & 1, kb = i >> 6;
        int k0 = kb * 8 + (ln & 3);
        const float* wr0 = W_hh + (col0 + np * 16 + (ln >> 2)) * H;
        const float* wr1 = wr0 + 8 * H;
        float w00 = wr0[k0], w01 = wr0[k0 + 4];
        float w10 = wr1[k0], w11 = wr1[k0 + 4];
        float4 hi, lo;
        hi.x = tf32_rna(w00); lo.x = tf32_rna(w00 - hi.x);
        hi.y = tf32_rna(w01); lo.y = tf32_rna(w01 - hi.y);
        hi.z = tf32_rna(w10); lo.z = tf32_rna(w10 - hi.z);
        hi.w = tf32_rna(w11); lo.w = tf32_rna(w11 - hi.w);
        *(float4*)(smem + SM_B + i * 16)           = hi;
        *(float4*)(smem + SM_B + B_PLANE + i * 16) = lo;
    }
    if (tid < BN) {
        wxs[tid] = W_hx[col0 + tid];
        bbs[tid] = b_hx[col0 + tid] + b_hh[col0 + tid];
    }
    {   // h0 = zeros; each CTA zeroes a disjoint 1/128 slice
        int cta = rb * CBX + cb;
        for (int i = tid; i < 2048; i += NTHR) g_h[0][cta * 2048 + i] = 0.0f;
    }
    grid_barrier(1u);

    // staging roles: rows srow, srow+32; k-float4 sfc, sfc+16 within a 128-k chunk
    const int srow = tid >> 4, sfc = tid & 15;
    // fragment base (bytes): row mg*32 + lane/4, k word lane%4 (k-major stride 132)
    const int aoff = ((mg * 32 + (lane >> 2)) * 132 + (lane & 3)) * 4;

    for (int t = 0; t < S; ++t) {
        const float* hin  = g_h[t & 1];
        float*       hout = g_h[(t + 1) & 1];
        if (tid < BM) xs[tid] = x[(row0 + tid) * S + t];

        const float* hp0 = hin + (row0 + srow) * H + sfc * 4;
        const float* hp1 = hp0 + 32 * H;

        {   // stage chunk 0 into buf 0
            float4 a0 = *(const float4*)(hp0);
            float4 a1 = *(const float4*)(hp0 + 64);
            float4 b0 = *(const float4*)(hp1);
            float4 b1 = *(const float4*)(hp1 + 64);
            char* base = smem + SM_A;
            *(float4*)(base + (srow * 132 + sfc * 4) * 4)          = a0;
            *(float4*)(base + (srow * 132 + (sfc + 16) * 4) * 4)   = a1;
            *(float4*)(base + ((srow + 32) * 132 + sfc * 4) * 4)        = b0;
            *(float4*)(base + ((srow + 32) * 132 + (sfc + 16) * 4) * 4) = b1;
        }

        float D[2][4][4];
        #pragma unroll
        for (int rg = 0; rg < 2; ++rg)
            #pragma unroll
            for (int nb = 0; nb < 4; ++nb)
                #pragma unroll
                for (int r = 0; r < 4; ++r) D[rg][nb][r] = 0.0f;

        float4 pa0, pa1, pb0, pb1;
        #pragma unroll
        for (int c = 0; c < NCH; ++c) {
            __syncthreads();                   // chunk c staged; buf (c+1)&1 free
            if (c + 1 < NCH) {                 // prefetch next chunk (L1/L2)
                pa0 = *(const float4*)(hp0 + (c + 1) * 128);
                pa1 = *(const float4*)(hp0 + (c + 1) * 128 + 64);
                pb0 = *(const float4*)(hp1 + (c + 1) * 128);
                pb1 = *(const float4*)(hp1 + (c + 1) * 128 + 64);
            }
            const char* abc = smem + SM_A + (c & 1) * A_BUF + aoff;
            #pragma unroll
            for (int j = 0; j < 2; ++j) {
                const char* bbp = smem + SM_B
                                + (size_t)(c * 16 + kg * 2 + j) * 1024 + lane * 16;
                float4 bh0 = *(const float4*)(bbp);
                float4 bh1 = *(const float4*)(bbp + 512);
                float4 bl0 = *(const float4*)(bbp + B_PLANE);
                float4 bl1 = *(const float4*)(bbp + B_PLANE + 512);
                uint32_t BH[8] = { fu(bh0.x), fu(bh0.y), fu(bh0.z), fu(bh0.w),
                                   fu(bh1.x), fu(bh1.y), fu(bh1.z), fu(bh1.w) };
                uint32_t BL[8] = { fu(bl0.x), fu(bl0.y), fu(bl0.z), fu(bl0.w),
                                   fu(bl1.x), fu(bl1.y), fu(bl1.z), fu(bl1.w) };
                const char* ab = abc + (kg * 16 + j * 8) * 4;
                #pragma unroll
                for (int rg = 0; rg < 2; ++rg) {
                    const char* ar = ab + rg * (16 * 132 * 4);
                    float f0 = *(const float*)(ar);
                    float f1 = *(const float*)(ar + 8 * 132 * 4);
                    float f2 = *(const float*)(ar + 16);
                    float f3 = *(const float*)(ar + 8 * 132 * 4 + 16);
                    float h0 = tf32_rna(f0), h1 = tf32_rna(f1);
                    float h2 = tf32_rna(f2), h3 = tf32_rna(f3);
                    uint32_t ah0 = fu(h0), ah1 = fu(h1), ah2 = fu(h2), ah3 = fu(h3);
                    uint32_t al0 = fu(f0 - h0), al1 = fu(f1 - h1);
                    uint32_t al2 = fu(f2 - h2), al3 = fu(f3 - h3);
                    #pragma unroll
                    for (int nb = 0; nb < 4; ++nb) {
                        mma8(D[rg][nb], ah0, ah1, ah2, ah3, BH[2*nb], BH[2*nb+1]);
                        mma8(D[rg][nb], al0, al1, al2, al3, BH[2*nb], BH[2*nb+1]);
                        mma8(D[rg][nb], ah0, ah1, ah2, ah3, BL[2*nb], BL[2*nb+1]);
                    }
                }
            }
            if (c + 1 < NCH) {
                char* base = smem + SM_A + ((c + 1) & 1) * A_BUF;
                *(float4*)(base + (srow * 132 + sfc * 4) * 4)          = pa0;
                *(float4*)(base + (srow * 132 + (sfc + 16) * 4) * 4)   = pa1;
                *(float4*)(base + ((srow + 32) * 132 + sfc * 4) * 4)        = pb0;
                *(float4*)(base + ((srow + 32) * 132 + (sfc + 16) * 4) * 4) = pb1;
            }
        }
        __syncthreads();                       // compute done; A buffers reusable

        // scatter k-partials: mg0 -> buf0 region, mg1 -> buf1 region
        {
            float4* scr = (float4*)(smem + SM_A + mg * A_BUF);
            #pragma unroll
            for (int rg = 0; rg < 2; ++rg)
                #pragma unroll
                for (int nb = 0; nb < 4; ++nb)
                    scr[kg * 256 + rg * 128 + nb * 32 + lane] =
                        make_float4(D[rg][nb][0], D[rg][nb][1],
                                    D[rg][nb][2], D[rg][nb][3]);
        }
        __syncthreads();

        // Reduce 8 k-partials + epilogue: each thread finishes 4 outputs.
        {
            int mgp = tid >> 8, idx = tid & 255;
            const float4* scr = (const float4*)(smem + SM_A + mgp * A_BUF);
            float4 v = scr[idx];
            #pragma unroll
            for (int k2 = 1; k2 < 8; ++k2) {
                float4 p = scr[k2 * 256 + idx];
                v.x += p.x; v.y += p.y; v.z += p.z; v.w += p.w;
            }
            int rg = idx >> 7, nb = (idx >> 5) & 3, ln = idx & 31;
            int r1 = mgp * 32 + rg * 16 + (ln >> 2);
            int jc = nb * 8 + 2 * (ln & 3);
            float xv1 = xs[r1], xv2 = xs[r1 + 8];
            float wj0 = wxs[jc], wj1 = wxs[jc + 1];
            float bj0 = bbs[jc], bj1 = bbs[jc + 1];
            float2 o1, o2;
            o1.x = ftanh(fmaf(xv1, wj0, v.x) + bj0);
            o1.y = ftanh(fmaf(xv1, wj1, v.y) + bj1);
            o2.x = ftanh(fmaf(xv2, wj0, v.z) + bj0);
            o2.y = ftanh(fmaf(xv2, wj1, v.w) + bj1);
            *(float2*)(hout + (row0 + r1) * H + col0 + jc)     = o1;
            *(float2*)(hout + (row0 + r1 + 8) * H + col0 + jc) = o2;
        }
        // Only the 16 CTAs of this strip must agree; strips run independently.
        strip_barrier(rb, t == S - 1 ? 0u : (unsigned)(t + 2));
    }

    // Final projection + softmax: cb==0 CTA of each strip handles its 64 rows.
    // Strip barrier above already ordered the strip's final h writes.
    if (cb == 0) {
        float* wo = (float*)(smem + SM_A);              // 5120 floats
        for (int i = tid; i < OUTD * H; i += NTHR) wo[i] = W_oh[i];
        __syncthreads();
        const float* hf = g_h[0];
        int r = tid >> 3, q = tid & 7;                  // 8 threads/row, 64 k each
        float p[OUTD];
        #pragma unroll
        for (int od = 0; od < OUTD; ++od) p[od] = 0.f;
        const float* hr = hf + (row0 + r) * H + q * 64;
        for (int k = 0; k < 64; k += 4) {
            float4 hv = *(const float4*)(hr + k);
            #pragma unroll
            for (int od = 0; od < OUTD; ++od) {
                const float* wr = wo + od * H + q * 64 + k;
                p[od] += hv.x * wr[0] + hv.y * wr[1] + hv.z * wr[2] + hv.w * wr[3];
            }
        }
        float* pr = (float*)(smem + SM_A + 20480);      // 512 x 10 partials
        #pragma unroll
        for (int od = 0; od < OUTD; ++od) pr[tid * OUTD + od] = p[od];
        __syncthreads();
        if (tid < BM) {
            float o[OUTD];
            #pragma unroll
            for (int od = 0; od < OUTD; ++od) {
                float s0 = 0.f;
                #pragma unroll
                for (int j = 0; j < 8; ++j)
                    s0 += pr[(8 * tid + j) * OUTD + od];
                o[od] = s0 + b_oh[od];
            }
            float mx = o[0];
            #pragma unroll
            for (int od = 1; od < OUTD; ++od) mx = fmaxf(mx, o[od]);
            float ssum = 0.f;
            #pragma unroll
            for (int od = 0; od < OUTD; ++od) { o[od] = expf(o[od] - mx); ssum += o[od]; }
            float inv = 1.0f / ssum;
            #pragma unroll
            for (int od = 0; od < OUTD; ++od)
                out[(row0 + tid) * OUTD + od] = o[od] * inv;
        }
    }

    grid_barrier(0u);   // restore global phase for graph replay
}

extern "C" void kernel_launch(void* const* d_in, const int* in_sizes, int n_in,
                              void* d_out, int out_size) {
    const float* x    = (const float*)d_in[0];
    const float* W_hx = (const float*)d_in[1];
    const float* b_hx = (const float*)d_in[2];
    const float* W_hh = (const float*)d_in[3];
    const float* b_hh = (const float*)d_in[4];
    const float* W_oh = (const float*)d_in[5];
    const float* b_oh = (const float*)d_in[6];
    float* out = (float*)d_out;

    cudaFuncSetAttribute(rnn_kernel, cudaFuncAttributeMaxDynamicSharedMemorySize, SMEM_BYTES);
    rnn_kernel<<<dim3(CBX, RBY, 1), NTHR, SMEM_BYTES>>>(x, W_hx, b_hx, W_hh, b_hh, W_oh, b_oh, out);
}